// round 3
// baseline (speedup 1.0000x reference)
#include <cuda_runtime.h>
#include <cuda_bf16.h>
#include <math.h>

#define NB   2
#define CIN  256     // deform output channels O
#define CMID 128     // transconv output channels C
#define H0   64
#define W0   64
#define H    128
#define W    128
#define KK   9
#define KC   1152    // KK * CMID
#define NPIX 16384   // H*W
#define QTOT 32768   // NB * NPIX

// ---------------- device scratch (no mallocs allowed) ----------------
__device__ float g_up[NB][CMID][H][W];               // transposed-conv output
__device__ __nv_bfloat16 g_Sbhi[KC][QTOT];           // bilinear im2col, bf16 hi
__device__ __nv_bfloat16 g_Sblo[KC][QTOT];           // bf16 lo residual
__device__ __nv_bfloat16 g_Wahi[CIN][KC];            // GEMM A m-major, bf16 hi
__device__ __nv_bfloat16 g_Walo[CIN][KC];            // bf16 lo residual
__device__ float g_WB[CIN][KK][CMID];                // transconv weights [ci][tap][co]
__device__ int   g_tiy[NB][KK];
__device__ int   g_tix[NB][KK];
__device__ float g_twgt[NB][KK][4];

// ---------------- kernel A: offset net + tap precompute ----------------
__global__ void k_offsets(const float* __restrict__ lat,
                          const float* __restrict__ w1, const float* __restrict__ b1,
                          const float* __restrict__ w2, const float* __restrict__ b2) {
    __shared__ float sh[NB][64];
    __shared__ float soff[NB][18];
    int t = threadIdx.x;                 // 128 threads
    int n = t >> 6, o = t & 63;
    float acc = b1[o];
    for (int i = 0; i < CMID; i++)
        acc += lat[n * CMID + i] * w1[(o * CMID + i) * KK + 4];
    sh[n][o] = fmaxf(acc, 0.f);
    __syncthreads();
    if (t < NB * 18) {
        int nn = t / 18, j = t % 18;
        float a = b2[j];
        for (int q = 0; q < 64; q++)
            a += sh[nn][q] * w2[(j * 64 + q) * KK + 4];
        soff[nn][j] = tanhf(a);
    }
    __syncthreads();
    if (t < NB * KK) {
        int nn = t / KK, k = t % KK;
        float oy = soff[nn][2 * k], ox = soff[nn][2 * k + 1];
        float ay = (float)(k / 3 - 1) + oy;   // pad = 1
        float ax = (float)(k % 3 - 1) + ox;
        float fy = floorf(ay), fx = floorf(ax);
        float dy = ay - fy, dx = ax - fx;
        g_tiy[nn][k] = (int)fy;
        g_tix[nn][k] = (int)fx;
        g_twgt[nn][k][0] = (1.f - dy) * (1.f - dx);
        g_twgt[nn][k][1] = (1.f - dy) * dx;
        g_twgt[nn][k][2] = dy * (1.f - dx);
        g_twgt[nn][k][3] = dy * dx;
    }
}

// ---------------- weight re-layout + bf16 split ----------------
__global__ void k_wprep(const float* __restrict__ w) {
    int e = blockIdx.x * 256 + threadIdx.x;   // < 294912 = 256*1152
    {   // GEMM A (m-major): g_Wa[o][kc] = w[(o*128 + c)*9 + k], kc = k*128 + c
        int o  = e / KC;
        int kc = e - o * KC;
        int c  = kc & 127, k = kc >> 7;
        float v = w[(o * CMID + c) * KK + k];
        __nv_bfloat16 hi = __float2bfloat16(v);
        __nv_bfloat16 lo = __float2bfloat16(v - __bfloat162float(hi));
        g_Wahi[o][kc] = hi;
        g_Walo[o][kc] = lo;
    }
    {   // transconv: g_WB[ci][tap][co]
        int ci  = e / KC;
        int r   = e - ci * KC;
        int tap = r >> 7;
        int co  = r & 127;
        g_WB[ci][tap][co] = w[(ci * CMID + co) * KK + tap];
    }
}

// ---------------- kernel B: stride-2 transposed conv (parity decomposed) ----------------
#define VBODY(XR, KYV) do {                                                          \
    int kyb = (KYV) * 3;                                                             \
    float wreg[8];                                                                   \
    _Pragma("unroll") for (int c = 0; c < 8; c++) wreg[c] = sW[cc][kyb + 1][co0 + c];\
    _Pragma("unroll") for (int p = 0; p < 8; p += 2) {                               \
        float xv = XR[p >> 1];                                                       \
        _Pragma("unroll") for (int c = 0; c < 8; c++)                                \
            acc[c][p] = fmaf(xv, wreg[c], acc[c][p]);                                \
    }                                                                                \
    _Pragma("unroll") for (int c = 0; c < 8; c++) wreg[c] = sW[cc][kyb + 0][co0 + c];\
    _Pragma("unroll") for (int p = 1; p < 8; p += 2) {                               \
        float xv = XR[(p + 1) >> 1];                                                 \
        _Pragma("unroll") for (int c = 0; c < 8; c++)                                \
            acc[c][p] = fmaf(xv, wreg[c], acc[c][p]);                                \
    }                                                                                \
    _Pragma("unroll") for (int c = 0; c < 8; c++) wreg[c] = sW[cc][kyb + 2][co0 + c];\
    _Pragma("unroll") for (int p = 1; p < 8; p += 2) {                               \
        float xv = XR[p >> 1];                                                       \
        _Pragma("unroll") for (int c = 0; c < 8; c++)                                \
            acc[c][p] = fmaf(xv, wreg[c], acc[c][p]);                                \
    }                                                                                \
} while (0)

__global__ __launch_bounds__(256, 2) void k_transconv(const float* __restrict__ x) {
    const int Y = blockIdx.x;
    const int n = blockIdx.y;
    const int t = threadIdx.x;
    const int xg = t & 15, cg = t >> 4;
    const int X0 = xg << 3, co0 = cg << 3, jb = xg << 2;

    int nv, vky0, vi0, vky1 = 0, vi1 = 0;
    if ((Y & 1) == 0) { nv = 1; vky0 = 1; vi0 = Y >> 1; }
    else {
        int ia = (Y + 1) >> 1;
        if (ia < H0) { nv = 2; vky0 = 0; vi0 = ia; vky1 = 2; vi1 = Y >> 1; }
        else         { nv = 1; vky0 = 2; vi0 = Y >> 1; }
    }

    __shared__ float sX[8][2][64];
    __shared__ float sW[8][KK][CMID];

    float acc[8][8];
    #pragma unroll
    for (int c = 0; c < 8; c++)
        #pragma unroll
        for (int p = 0; p < 8; p++) acc[c][p] = 0.f;

    const float* wb = &g_WB[0][0][0];

    for (int ci0 = 0; ci0 < CIN; ci0 += 8) {
        __syncthreads();
        {
            int sh = (nv == 2) ? 7 : 6;
            int tot = 8 << sh;
            for (int e = t; e < tot; e += 256) {
                int cc = e >> sh;
                int rr = e & ((1 << sh) - 1);
                int v  = rr >> 6, j = rr & 63;
                int irow = v ? vi1 : vi0;
                sX[cc][v][j] = x[((n * CIN + ci0 + cc) * H0 + irow) * W0 + j];
            }
        }
        {
            const float* src = wb + ci0 * (KK * CMID);
            float* dst = &sW[0][0][0];
            for (int e = t; e < 8 * KK * CMID; e += 256) dst[e] = src[e];
        }
        __syncthreads();

        #pragma unroll
        for (int cc = 0; cc < 8; cc++) {
            float xr0[5], xr1[5];
            #pragma unroll
            for (int u = 0; u < 5; u++) {
                int j = jb + u;
                xr0[u] = (j < W0) ? sX[cc][0][j] : 0.f;
                xr1[u] = (nv > 1 && j < W0) ? sX[cc][1][j] : 0.f;
            }
            VBODY(xr0, vky0);
            if (nv > 1) VBODY(xr1, vky1);
        }
    }

    #pragma unroll
    for (int c = 0; c < 8; c++) {
        float* dst = &g_up[n][co0 + c][Y][X0];
        reinterpret_cast<float4*>(dst)[0] =
            make_float4(acc[c][0], acc[c][1], acc[c][2], acc[c][3]);
        reinterpret_cast<float4*>(dst)[1] =
            make_float4(acc[c][4], acc[c][5], acc[c][6], acc[c][7]);
    }
}

// ---------------- kernel C1: bilinear gather -> bf16 hi/lo split ----------------
__global__ void k_sample() {
    int idx = blockIdx.x * 256 + threadIdx.x;
    int e = idx << 2;
    int x0 = e & 127;
    int y  = (e >> 7) & 127;
    int n  = (e >> 14) & 1;
    int kc = e >> 15;
    int c  = kc & 127, k = kc >> 7;

    int iy = g_tiy[n][k], ix = g_tix[n][k];
    float w00 = g_twgt[n][k][0], w01 = g_twgt[n][k][1];
    float w10 = g_twgt[n][k][2], w11 = g_twgt[n][k][3];

    const float* U = &g_up[n][c][0][0];
    int r0 = y + iy, r1 = r0 + 1;
    bool v0 = (r0 >= 0) && (r0 < H);
    bool v1 = (r1 >= 0) && (r1 < H);
    int cb = x0 + ix;

    float row0[5], row1[5];
    #pragma unroll
    for (int u = 0; u < 5; u++) {
        int col = cb + u;
        bool vc = (col >= 0) && (col < W);
        row0[u] = (v0 && vc) ? U[r0 * W + col] : 0.f;
        row1[u] = (v1 && vc) ? U[r1 * W + col] : 0.f;
    }
    float v[4];
    v[0] = w00 * row0[0] + w01 * row0[1] + w10 * row1[0] + w11 * row1[1];
    v[1] = w00 * row0[1] + w01 * row0[2] + w10 * row1[1] + w11 * row1[2];
    v[2] = w00 * row0[2] + w01 * row0[3] + w10 * row1[2] + w11 * row1[3];
    v[3] = w00 * row0[3] + w01 * row0[4] + w10 * row1[3] + w11 * row1[4];

    __nv_bfloat162 hp0, hp1, lp0, lp1;
    __nv_bfloat16 h0 = __float2bfloat16(v[0]);
    __nv_bfloat16 h1 = __float2bfloat16(v[1]);
    __nv_bfloat16 h2 = __float2bfloat16(v[2]);
    __nv_bfloat16 h3 = __float2bfloat16(v[3]);
    hp0.x = h0; hp0.y = h1; hp1.x = h2; hp1.y = h3;
    lp0.x = __float2bfloat16(v[0] - __bfloat162float(h0));
    lp0.y = __float2bfloat16(v[1] - __bfloat162float(h1));
    lp1.x = __float2bfloat16(v[2] - __bfloat162float(h2));
    lp1.y = __float2bfloat16(v[3] - __bfloat162float(h3));

    int q0 = (n << 14) + (y << 7) + x0;
    __nv_bfloat162* dh = reinterpret_cast<__nv_bfloat162*>(&g_Sbhi[kc][q0]);
    dh[0] = hp0; dh[1] = hp1;
    __nv_bfloat162* dl = reinterpret_cast<__nv_bfloat162*>(&g_Sblo[kc][q0]);
    dl[0] = lp0; dl[1] = lp1;
}

// ---------------- kernel C2: split-bf16 tensor-core GEMM ----------------
// C[o][q] = sum over K_eff=3456: seg0 Ahi*Bhi, seg1 Alo*Bhi, seg2 Ahi*Blo
#define BK    32
#define NT    108          // 3456 / 32
#define SEGT  36           // 1152 / 32
#define LDP   40           // padded smem row stride (bf16 elems)

__device__ __forceinline__ void mma16816(float* c, const unsigned* a, const unsigned* b) {
    asm volatile(
        "mma.sync.aligned.m16n8k16.row.col.f32.bf16.bf16.f32 "
        "{%0,%1,%2,%3}, {%4,%5,%6,%7}, {%8,%9}, {%0,%1,%2,%3};"
        : "+f"(c[0]), "+f"(c[1]), "+f"(c[2]), "+f"(c[3])
        : "r"(a[0]), "r"(a[1]), "r"(a[2]), "r"(a[3]), "r"(b[0]), "r"(b[1]));
}

__global__ __launch_bounds__(256, 2) void k_gemm(float* __restrict__ out) {
    const int nb = blockIdx.x;           // 256 blocks of 128 q
    const int mb = blockIdx.y;           // 2 blocks of 128 o
    const int t  = threadIdx.x;
    const int wid = t >> 5, lane = t & 31;
    const int gid = lane >> 2, tig = lane & 3;
    const int wm = wid >> 2, wn = wid & 3;     // warps 2(m) x 4(n)
    const int m0 = mb * 128, n0 = nb * 128;

    __shared__ __nv_bfloat16 As[2][128][LDP];
    __shared__ __nv_bfloat16 Bs[2][128][LDP];

    float acc[4][4][4];
    #pragma unroll
    for (int i = 0; i < 4; i++)
        #pragma unroll
        for (int j = 0; j < 4; j++)
            #pragma unroll
            for (int c = 0; c < 4; c++) acc[i][j][c] = 0.f;

    // staging coords
    const int a_kp = (t & 15) * 2;       // bf16 col pair base within BK
    const int a_mb0 = t >> 4;            // + i*16, i<8 -> 128 rows
    const int b_qp = (t & 63) * 2;       // q pair base within 128
    const int b_kb0 = t >> 6;            // + i*4,  i<8 -> 32 k rows

    const __nv_bfloat16* Ahi = &g_Wahi[0][0];
    const __nv_bfloat16* Alo = &g_Walo[0][0];
    const __nv_bfloat16* Bhi = &g_Sbhi[0][0];
    const __nv_bfloat16* Blo = &g_Sblo[0][0];

    unsigned ua[8], ub[8];

    // ---- prologue: stage tile 0 (seg 0: Ahi, Bhi; k0 = 0) ----
    #pragma unroll
    for (int i = 0; i < 8; i++)
        ua[i] = *(const unsigned*)&Ahi[(m0 + a_mb0 + i * 16) * KC + a_kp];
    #pragma unroll
    for (int i = 0; i < 8; i++)
        ub[i] = *(const unsigned*)&Bhi[(size_t)(b_kb0 + i * 4) * QTOT + n0 + b_qp];
    #pragma unroll
    for (int i = 0; i < 8; i++)
        *(unsigned*)&As[0][a_mb0 + i * 16][a_kp] = ua[i];
    #pragma unroll
    for (int i = 0; i < 8; i++) {
        __nv_bfloat162 v = *reinterpret_cast<__nv_bfloat162*>(&ub[i]);
        Bs[0][b_qp][b_kb0 + i * 4]     = v.x;
        Bs[0][b_qp + 1][b_kb0 + i * 4] = v.y;
    }
    __syncthreads();

    for (int kt = 0; kt < NT; kt++) {
        const int cur = kt & 1;
        const bool more = (kt + 1 < NT);
        if (more) {
            int kn = kt + 1;
            int seg = kn / SEGT;
            int k0  = (kn - seg * SEGT) * BK;
            const __nv_bfloat16* Ag = (seg == 1) ? Alo : Ahi;
            const __nv_bfloat16* Bg = (seg == 2) ? Blo : Bhi;
            #pragma unroll
            for (int i = 0; i < 8; i++)
                ua[i] = *(const unsigned*)&Ag[(m0 + a_mb0 + i * 16) * KC + k0 + a_kp];
            #pragma unroll
            for (int i = 0; i < 8; i++)
                ub[i] = *(const unsigned*)&Bg[(size_t)(k0 + b_kb0 + i * 4) * QTOT + n0 + b_qp];
        }

        #pragma unroll
        for (int ks = 0; ks < 2; ks++) {
            unsigned a[4][4], b[4][2];
            const int kb = ks * 16 + tig * 2;
            #pragma unroll
            for (int mf = 0; mf < 4; mf++) {
                int row = wm * 64 + mf * 16 + gid;
                a[mf][0] = *(const unsigned*)&As[cur][row][kb];
                a[mf][1] = *(const unsigned*)&As[cur][row + 8][kb];
                a[mf][2] = *(const unsigned*)&As[cur][row][kb + 8];
                a[mf][3] = *(const unsigned*)&As[cur][row + 8][kb + 8];
            }
            #pragma unroll
            for (int nf = 0; nf < 4; nf++) {
                int col = wn * 32 + nf * 8 + gid;
                b[nf][0] = *(const unsigned*)&Bs[cur][col][kb];
                b[nf][1] = *(const unsigned*)&Bs[cur][col][kb + 8];
            }
            #pragma unroll
            for (int mf = 0; mf < 4; mf++)
                #pragma unroll
                for (int nf = 0; nf < 4; nf++)
                    mma16816(acc[mf][nf], a[mf], b[nf]);
        }

        if (more) {
            const int nxt = cur ^ 1;
            #pragma unroll
            for (int i = 0; i < 8; i++)
                *(unsigned*)&As[nxt][a_mb0 + i * 16][a_kp] = ua[i];
            #pragma unroll
            for (int i = 0; i < 8; i++) {
                __nv_bfloat162 v = *reinterpret_cast<__nv_bfloat162*>(&ub[i]);
                Bs[nxt][b_qp][b_kb0 + i * 4]     = v.x;
                Bs[nxt][b_qp + 1][b_kb0 + i * 4] = v.y;
            }
        }
        __syncthreads();
    }

    // ---- epilogue ----
    #pragma unroll
    for (int mf = 0; mf < 4; mf++) {
        int o = m0 + wm * 64 + mf * 16 + gid;
        #pragma unroll
        for (int nf = 0; nf < 4; nf++) {
            int q = n0 + wn * 32 + nf * 8 + tig * 2;
            int nbat = q >> 14;
            int pix  = q & 16383;
            float* d0 = out + ((size_t)nbat * CIN + o) * NPIX + pix;
            *reinterpret_cast<float2*>(d0) = make_float2(acc[mf][nf][0], acc[mf][nf][1]);
            float* d1 = out + ((size_t)nbat * CIN + o + 8) * NPIX + pix;
            *reinterpret_cast<float2*>(d1) = make_float2(acc[mf][nf][2], acc[mf][nf][3]);
        }
    }
}

// ---------------- launch ----------------
extern "C" void kernel_launch(void* const* d_in, const int* in_sizes, int n_in,
                              void* d_out, int out_size) {
    const float* x   = (const float*)d_in[0];   // [2,256,64,64]
    const float* lat = (const float*)d_in[1];   // [2,128,1,1]
    const float* tw  = (const float*)d_in[2];   // [256,128,3,3]
    const float* w1  = (const float*)d_in[3];   // [64,128,3,3]
    const float* b1  = (const float*)d_in[4];   // [64]
    const float* w2  = (const float*)d_in[5];   // [18,64,3,3]
    const float* b2  = (const float*)d_in[6];   // [18]
    float* out = (float*)d_out;                 // [2,256,128,128]

    k_offsets<<<1, 128>>>(lat, w1, b1, w2, b2);
    k_wprep<<<1152, 256>>>(tw);
    k_transconv<<<dim3(128, 2), 256>>>(x);
    k_sample<<<36864, 256>>>();
    k_gemm<<<dim3(256, 2), 256>>>(out);
}

// round 6
// speedup vs baseline: 1.5401x; 1.5401x over previous
#include <cuda_runtime.h>
#include <cuda_fp16.h>
#include <cstdint>
#include <math.h>

#define NB   2
#define CIN  256     // deform output channels O (GEMM M)
#define CMID 128     // transconv output channels
#define H0   64
#define W0   64
#define H    128
#define W    128
#define KK   9
#define KC   1152    // KK * CMID
#define K2   2304    // A hi|lo concatenated
#define NPIX 16384
#define QTOT 32768   // GEMM N total

// ---------------- device scratch ----------------
__device__ float  g_up[NB][CMID][H][W];      // transposed-conv output
__device__ __half g_ST[QTOT][KC];            // im2col, [q][kc] K-contiguous, fp16
__device__ __half g_Wa[CIN][K2];             // weights: [o][0..1151]=hi, [1152..]=lo
__device__ float  g_WB[CIN][KK][CMID];       // transconv weights [ci][tap][co]
__device__ int    g_tiy[NB][KK];
__device__ int    g_tix[NB][KK];
__device__ float  g_twgt[NB][KK][4];

__device__ __forceinline__ uint32_t smem_u32(const void* p) {
    uint32_t a;
    asm("{ .reg .u64 t; cvta.to.shared.u64 t, %1; cvt.u32.u64 %0, t; }" : "=r"(a) : "l"(p));
    return a;
}

#define CP16(sm, gp) \
    asm volatile("cp.async.cg.shared.global [%0], [%1], 16;" :: "r"(sm), "l"(gp) : "memory")
#define CP_COMMIT() asm volatile("cp.async.commit_group;" ::: "memory")
#define CP_WAIT1()  asm volatile("cp.async.wait_group 1;" ::: "memory")
#define CP_WAIT0()  asm volatile("cp.async.wait_group 0;" ::: "memory")

#define LDSM4(R0, R1, R2, R3, a) \
    asm volatile("ldmatrix.sync.aligned.m8n8.x4.shared.b16 {%0,%1,%2,%3}, [%4];" \
                 : "=r"(R0), "=r"(R1), "=r"(R2), "=r"(R3) : "r"(a))

__device__ __forceinline__ void mma_f16(float* c, const uint32_t* a, const uint32_t* b) {
    asm volatile(
        "mma.sync.aligned.m16n8k16.row.col.f32.f16.f16.f32 "
        "{%0,%1,%2,%3}, {%4,%5,%6,%7}, {%8,%9}, {%0,%1,%2,%3};"
        : "+f"(c[0]), "+f"(c[1]), "+f"(c[2]), "+f"(c[3])
        : "r"(a[0]), "r"(a[1]), "r"(a[2]), "r"(a[3]), "r"(b[0]), "r"(b[1]));
}

// ---------------- kernel A: offset net + tap precompute ----------------
__global__ void k_offsets(const float* __restrict__ lat,
                          const float* __restrict__ w1, const float* __restrict__ b1,
                          const float* __restrict__ w2, const float* __restrict__ b2) {
    __shared__ float sh[NB][64];
    __shared__ float soff[NB][18];
    int t = threadIdx.x;
    int n = t >> 6, o = t & 63;
    float acc = b1[o];
    for (int i = 0; i < CMID; i++)
        acc += lat[n * CMID + i] * w1[(o * CMID + i) * KK + 4];
    sh[n][o] = fmaxf(acc, 0.f);
    __syncthreads();
    if (t < NB * 18) {
        int nn = t / 18, j = t % 18;
        float a = b2[j];
        for (int q = 0; q < 64; q++)
            a += sh[nn][q] * w2[(j * 64 + q) * KK + 4];
        soff[nn][j] = tanhf(a);
    }
    __syncthreads();
    if (t < NB * KK) {
        int nn = t / KK, k = t % KK;
        float oy = soff[nn][2 * k], ox = soff[nn][2 * k + 1];
        float ay = (float)(k / 3 - 1) + oy;
        float ax = (float)(k % 3 - 1) + ox;
        float fy = floorf(ay), fx = floorf(ax);
        float dy = ay - fy, dx = ax - fx;
        g_tiy[nn][k] = (int)fy;
        g_tix[nn][k] = (int)fx;
        g_twgt[nn][k][0] = (1.f - dy) * (1.f - dx);
        g_twgt[nn][k][1] = (1.f - dy) * dx;
        g_twgt[nn][k][2] = dy * (1.f - dx);
        g_twgt[nn][k][3] = dy * dx;
    }
}

// ---------------- weight re-layout + fp16 split ----------------
__global__ void k_wprep(const float* __restrict__ w) {
    int e = blockIdx.x * 256 + threadIdx.x;   // < 294912 = 256*1152
    {   // A: g_Wa[o][kc]=hi, g_Wa[o][1152+kc]=lo ; kc = k*128 + c
        int o  = e / KC;
        int kc = e - o * KC;
        int c  = kc & 127, k = kc >> 7;
        float v = w[(o * CMID + c) * KK + k];
        __half hi = __float2half_rn(v);
        __half lo = __float2half_rn(v - __half2float(hi));
        g_Wa[o][kc] = hi;
        g_Wa[o][KC + kc] = lo;
    }
    {   // transconv: g_WB[ci][tap][co]
        int ci  = e / KC;
        int r   = e - ci * KC;
        int tap = r >> 7;
        int co  = r & 127;
        g_WB[ci][tap][co] = w[(ci * CMID + co) * KK + tap];
    }
}

// ---------------- kernel B: stride-2 transposed conv (unchanged, fp32) ----------------
#define VBODY(XR, KYV) do {                                                          \
    int kyb = (KYV) * 3;                                                             \
    float wreg[8];                                                                   \
    _Pragma("unroll") for (int c = 0; c < 8; c++) wreg[c] = sW[cc][kyb + 1][co0 + c];\
    _Pragma("unroll") for (int p = 0; p < 8; p += 2) {                               \
        float xv = XR[p >> 1];                                                       \
        _Pragma("unroll") for (int c = 0; c < 8; c++)                                \
            acc[c][p] = fmaf(xv, wreg[c], acc[c][p]);                                \
    }                                                                                \
    _Pragma("unroll") for (int c = 0; c < 8; c++) wreg[c] = sW[cc][kyb + 0][co0 + c];\
    _Pragma("unroll") for (int p = 1; p < 8; p += 2) {                               \
        float xv = XR[(p + 1) >> 1];                                                 \
        _Pragma("unroll") for (int c = 0; c < 8; c++)                                \
            acc[c][p] = fmaf(xv, wreg[c], acc[c][p]);                                \
    }                                                                                \
    _Pragma("unroll") for (int c = 0; c < 8; c++) wreg[c] = sW[cc][kyb + 2][co0 + c];\
    _Pragma("unroll") for (int p = 1; p < 8; p += 2) {                               \
        float xv = XR[p >> 1];                                                       \
        _Pragma("unroll") for (int c = 0; c < 8; c++)                                \
            acc[c][p] = fmaf(xv, wreg[c], acc[c][p]);                                \
    }                                                                                \
} while (0)

__global__ __launch_bounds__(256, 2) void k_transconv(const float* __restrict__ x) {
    const int Y = blockIdx.x;
    const int n = blockIdx.y;
    const int t = threadIdx.x;
    const int xg = t & 15, cg = t >> 4;
    const int X0 = xg << 3, co0 = cg << 3, jb = xg << 2;

    int nv, vky0, vi0, vky1 = 0, vi1 = 0;
    if ((Y & 1) == 0) { nv = 1; vky0 = 1; vi0 = Y >> 1; }
    else {
        int ia = (Y + 1) >> 1;
        if (ia < H0) { nv = 2; vky0 = 0; vi0 = ia; vky1 = 2; vi1 = Y >> 1; }
        else         { nv = 1; vky0 = 2; vi0 = Y >> 1; }
    }

    __shared__ float sX[8][2][64];
    __shared__ float sW[8][KK][CMID];

    float acc[8][8];
    #pragma unroll
    for (int c = 0; c < 8; c++)
        #pragma unroll
        for (int p = 0; p < 8; p++) acc[c][p] = 0.f;

    const float* wb = &g_WB[0][0][0];

    for (int ci0 = 0; ci0 < CIN; ci0 += 8) {
        __syncthreads();
        {
            int sh = (nv == 2) ? 7 : 6;
            int tot = 8 << sh;
            for (int e = t; e < tot; e += 256) {
                int cc = e >> sh;
                int rr = e & ((1 << sh) - 1);
                int v  = rr >> 6, j = rr & 63;
                int irow = v ? vi1 : vi0;
                sX[cc][v][j] = x[((n * CIN + ci0 + cc) * H0 + irow) * W0 + j];
            }
        }
        {
            const float* src = wb + ci0 * (KK * CMID);
            float* dst = &sW[0][0][0];
            for (int e = t; e < 8 * KK * CMID; e += 256) dst[e] = src[e];
        }
        __syncthreads();

        #pragma unroll
        for (int cc = 0; cc < 8; cc++) {
            float xr0[5], xr1[5];
            #pragma unroll
            for (int u = 0; u < 5; u++) {
                int j = jb + u;
                xr0[u] = (j < W0) ? sX[cc][0][j] : 0.f;
                xr1[u] = (nv > 1 && j < W0) ? sX[cc][1][j] : 0.f;
            }
            VBODY(xr0, vky0);
            if (nv > 1) VBODY(xr1, vky1);
        }
    }

    #pragma unroll
    for (int c = 0; c < 8; c++) {
        float* dst = &g_up[n][co0 + c][Y][X0];
        reinterpret_cast<float4*>(dst)[0] =
            make_float4(acc[c][0], acc[c][1], acc[c][2], acc[c][3]);
        reinterpret_cast<float4*>(dst)[1] =
            make_float4(acc[c][4], acc[c][5], acc[c][6], acc[c][7]);
    }
}

// ---------------- kernel C1: bilinear gather -> transposed [q][kc] fp16 ----------------
// grid (18, 256): blockIdx.x = kc-block (64 kc), blockIdx.y = n*128 + y
__global__ __launch_bounds__(256) void k_sample() {
    __shared__ float s_t[64][133];
    const int kb = blockIdx.x;
    const int by = blockIdx.y;
    const int n = by >> 7, y = by & 127;
    const int kc0 = kb * 64;
    const int k = kc0 >> 7;            // tap (constant over block)
    const int c0 = kc0 & 127;
    const int t = threadIdx.x;

    const int iy = g_tiy[n][k], ix = g_tix[n][k];
    const float w00 = g_twgt[n][k][0], w01 = g_twgt[n][k][1];
    const float w10 = g_twgt[n][k][2], w11 = g_twgt[n][k][3];

    const int r0 = y + iy, r1 = r0 + 1;
    const bool v0 = (r0 >= 0) && (r0 < H);
    const bool v1 = (r1 >= 0) && (r1 < H);

    #pragma unroll
    for (int it = 0; it < 8; it++) {
        int e = t + it * 256;           // < 2048
        int kcl = e >> 5;               // 0..63
        int xq  = e & 31;
        int x0  = xq << 2;
        const float* U = &g_up[n][c0 + kcl][0][0];
        int cb = x0 + ix;
        float row0[5], row1[5];
        #pragma unroll
        for (int u = 0; u < 5; u++) {
            int col = cb + u;
            bool vc = (col >= 0) && (col < W);
            row0[u] = (v0 && vc) ? U[r0 * W + col] : 0.f;
            row1[u] = (v1 && vc) ? U[r1 * W + col] : 0.f;
        }
        s_t[kcl][x0 + 0] = w00 * row0[0] + w01 * row0[1] + w10 * row1[0] + w11 * row1[1];
        s_t[kcl][x0 + 1] = w00 * row0[1] + w01 * row0[2] + w10 * row1[1] + w11 * row1[2];
        s_t[kcl][x0 + 2] = w00 * row0[2] + w01 * row0[3] + w10 * row1[2] + w11 * row1[3];
        s_t[kcl][x0 + 3] = w00 * row0[3] + w01 * row0[4] + w10 * row1[3] + w11 * row1[4];
    }
    __syncthreads();

    #pragma unroll
    for (int it = 0; it < 4; it++) {
        int f = t + it * 256;           // < 1024
        int x  = f >> 3;
        int u8 = f & 7;
        uint32_t hw[4];
        #pragma unroll
        for (int p = 0; p < 4; p++) {
            __half2 h2;
            h2.x = __float2half_rn(s_t[u8 * 8 + 2 * p][x]);
            h2.y = __float2half_rn(s_t[u8 * 8 + 2 * p + 1][x]);
            hw[p] = *reinterpret_cast<uint32_t*>(&h2);
        }
        size_t q = ((size_t)n << 14) + (y << 7) + x;
        *reinterpret_cast<uint4*>(&g_ST[q][kc0 + u8 * 8]) =
            make_uint4(hw[0], hw[1], hw[2], hw[3]);
    }
}

// ---------------- kernel C2: 2-segment fp16 HMMA GEMM ----------------
// C[o][q] = sum_{kc} (Whi + Wlo)[o][kc] * S[q][kc],  K_eff = 2304, 72 tiles of 32
#define BK      32
#define NTILE   72
#define SEGT    36
#define LDH     40            // padded smem row stride in halves (80B)
#define STG     (128 * LDH)   // halves per stage

__global__ __launch_bounds__(256, 2) void k_gemm(float* __restrict__ out) {
    __shared__ __half As[2][128][LDH];
    __shared__ __half Bs[2][128][LDH];

    const int nb = blockIdx.x;           // 256 N-blocks of 128 q
    const int mb = blockIdx.y;           // 2 M-blocks of 128 o
    const int t  = threadIdx.x;
    const int wid = t >> 5, lane = t & 31;
    const int gid = lane >> 2, tig = lane & 3;
    const int lr = lane & 7, lm = lane >> 3;   // ldmatrix row / matrix id
    const int wm = wid >> 2, wn = wid & 3;     // warps 2(m) x 4(n)
    const int m0 = mb * 128, n0 = nb * 128;

    const uint32_t asb0 = smem_u32(&As[0][0][0]);
    const uint32_t bsb0 = smem_u32(&Bs[0][0][0]);

    // staging: 2 x 16B chunks per thread for A and B each
    const int sc0 = t * 2;
    const int srow0 = sc0 >> 2, su0 = sc0 & 3;
    const int srow1 = (sc0 + 1) >> 2, su1 = (sc0 + 1) & 3;

    const __half* Ab = &g_Wa[m0][0];
    const __half* Bb = &g_ST[n0][0];

    float acc[4][4][4];
    #pragma unroll
    for (int i = 0; i < 4; i++)
        #pragma unroll
        for (int j = 0; j < 4; j++)
            #pragma unroll
            for (int c = 0; c < 4; c++) acc[i][j][c] = 0.f;

    // ---- prologue: stage tile 0 into buffer 0 ----
    {
        const __half* Ag = Ab;                 // kidx = 0
        const __half* Bg = Bb;                 // k0b  = 0
        CP16(asb0 + srow0 * (LDH * 2) + su0 * 16, Ag + srow0 * K2 + su0 * 8);
        CP16(asb0 + srow1 * (LDH * 2) + su1 * 16, Ag + srow1 * K2 + su1 * 8);
        CP16(bsb0 + srow0 * (LDH * 2) + su0 * 16, Bg + (size_t)srow0 * KC + su0 * 8);
        CP16(bsb0 + srow1 * (LDH * 2) + su1 * 16, Bg + (size_t)srow1 * KC + su1 * 8);
        CP_COMMIT();
    }

    for (int kt = 0; kt < NTILE; kt++) {
        const int cur = kt & 1;
        if (kt + 1 < NTILE) {
            const int kn = kt + 1;
            const int kidx = (kn < SEGT) ? kn * BK : KC + (kn - SEGT) * BK;
            const int k0b  = (kn < SEGT) ? kn * BK : (kn - SEGT) * BK;
            const uint32_t as = asb0 + (cur ^ 1) * (STG * 2);
            const uint32_t bs = bsb0 + (cur ^ 1) * (STG * 2);
            const __half* Ag = Ab + kidx;
            const __half* Bg = Bb + k0b;
            CP16(as + srow0 * (LDH * 2) + su0 * 16, Ag + srow0 * K2 + su0 * 8);
            CP16(as + srow1 * (LDH * 2) + su1 * 16, Ag + srow1 * K2 + su1 * 8);
            CP16(bs + srow0 * (LDH * 2) + su0 * 16, Bg + (size_t)srow0 * KC + su0 * 8);
            CP16(bs + srow1 * (LDH * 2) + su1 * 16, Bg + (size_t)srow1 * KC + su1 * 8);
            CP_COMMIT();
            CP_WAIT1();
        } else {
            CP_WAIT0();
        }
        __syncthreads();

        const uint32_t as = asb0 + cur * (STG * 2);
        const uint32_t bs = bsb0 + cur * (STG * 2);

        #pragma unroll
        for (int ks = 0; ks < 2; ks++) {
            uint32_t a[4][4], b[4][2];
            #pragma unroll
            for (int mf = 0; mf < 4; mf++) {
                uint32_t row = wm * 64 + mf * 16 + ((lm & 1) << 3) + lr;
                uint32_t colb = ks * 32 + ((lm >> 1) << 4);
                LDSM4(a[mf][0], a[mf][1], a[mf][2], a[mf][3],
                      as + row * (LDH * 2) + colb);
            }
            #pragma unroll
            for (int np = 0; np < 2; np++) {
                uint32_t r0, r1, r2, r3;
                uint32_t row = wn * 32 + np * 16 + ((lm >> 1) << 3) + lr;
                uint32_t colb = ks * 32 + ((lm & 1) << 4);
                LDSM4(r0, r1, r2, r3, bs + row * (LDH * 2) + colb);
                b[2 * np][0] = r0; b[2 * np][1] = r1;
                b[2 * np + 1][0] = r2; b[2 * np + 1][1] = r3;
            }
            #pragma unroll
            for (int mf = 0; mf < 4; mf++)
                #pragma unroll
                for (int nf = 0; nf < 4; nf++)
                    mma_f16(acc[mf][nf], a[mf], b[nf]);
        }
        __syncthreads();   // all warps done reading cur before it is restaged
    }

    // ---- epilogue ----
    const int nbat = n0 >> 14;
    const int pix0 = n0 & 16383;
    #pragma unroll
    for (int mf = 0; mf < 4; mf++) {
        int o = m0 + wm * 64 + mf * 16 + gid;
        #pragma unroll
        for (int nf = 0; nf < 4; nf++) {
            int qoff = pix0 + wn * 32 + nf * 8 + tig * 2;
            float* d0 = out + ((size_t)nbat * CIN + o) * NPIX + qoff;
            *reinterpret_cast<float2*>(d0) = make_float2(acc[mf][nf][0], acc[mf][nf][1]);
            float* d1 = out + ((size_t)nbat * CIN + o + 8) * NPIX + qoff;
            *reinterpret_cast<float2*>(d1) = make_float2(acc[mf][nf][2], acc[mf][nf][3]);
        }
    }
}

// ---------------- launch ----------------
extern "C" void kernel_launch(void* const* d_in, const int* in_sizes, int n_in,
                              void* d_out, int out_size) {
    const float* x   = (const float*)d_in[0];   // [2,256,64,64]
    const float* lat = (const float*)d_in[1];   // [2,128,1,1]
    const float* tw  = (const float*)d_in[2];   // [256,128,3,3]
    const float* w1  = (const float*)d_in[3];   // [64,128,3,3]
    const float* b1  = (const float*)d_in[4];   // [64]
    const float* w2  = (const float*)d_in[5];   // [18,64,3,3]
    const float* b2  = (const float*)d_in[6];   // [18]
    float* out = (float*)d_out;                 // [2,256,128,128]

    k_offsets<<<1, 128>>>(lat, w1, b1, w2, b2);
    k_wprep<<<1152, 256>>>(tw);
    k_transconv<<<dim3(128, 2), 256>>>(x);
    k_sample<<<dim3(18, 256), 256>>>();
    k_gemm<<<dim3(256, 2), 256>>>(out);
}

// round 7
// speedup vs baseline: 3.2720x; 2.1245x over previous
#include <cuda_runtime.h>
#include <cuda_fp16.h>
#include <cstdint>
#include <math.h>

#define NB   2
#define CIN  256     // deform output channels O (GEMM M); also transconv input channels
#define CMID 128     // transconv output channels
#define H0   64
#define W0   64
#define H    128
#define W    128
#define KK   9
#define KC   1152    // KK * CMID
#define NPIX 16384
#define QTOT 32768   // GEMM N total
#define KTC  2304    // transconv class-grouped K total (256+512+512+1024)

// ---------------- device scratch ----------------
__device__ float  g_up[NB][CMID][H][W];      // transposed-conv output
__device__ __half g_ST[QTOT][KC];            // im2col, [q][kc] K-contiguous, fp16
__device__ __half g_Wa[CIN][KC];             // deform GEMM A, m-major k-contig, fp16
__device__ __half g_Wc[CMID][KTC];           // transconv GEMM A, class-grouped k
__device__ __half g_xhA[NB * CIN * 65 * 64]; // x fp16, padded (zero row u=64)
__device__ __half g_xhB[NB * CIN * 65 * 64]; // x shifted by +1 in j (zero fill)
__device__ int    g_tiy[NB][KK];
__device__ int    g_tix[NB][KK];
__device__ float  g_twgt[NB][KK][4];

__device__ __forceinline__ uint32_t smem_u32(const void* p) {
    uint32_t a;
    asm("{ .reg .u64 t; cvta.to.shared.u64 t, %1; cvt.u32.u64 %0, t; }" : "=r"(a) : "l"(p));
    return a;
}

#define CP16(sm, gp) \
    asm volatile("cp.async.cg.shared.global [%0], [%1], 16;" :: "r"(sm), "l"(gp) : "memory")
#define CP_COMMIT() asm volatile("cp.async.commit_group;" ::: "memory")
#define CP_WAIT1()  asm volatile("cp.async.wait_group 1;" ::: "memory")
#define CP_WAIT0()  asm volatile("cp.async.wait_group 0;" ::: "memory")

#define LDSM4(R0, R1, R2, R3, a) \
    asm volatile("ldmatrix.sync.aligned.m8n8.x4.shared.b16 {%0,%1,%2,%3}, [%4];" \
                 : "=r"(R0), "=r"(R1), "=r"(R2), "=r"(R3) : "r"(a))
#define LDSM4T(R0, R1, R2, R3, a) \
    asm volatile("ldmatrix.sync.aligned.m8n8.x4.trans.shared.b16 {%0,%1,%2,%3}, [%4];" \
                 : "=r"(R0), "=r"(R1), "=r"(R2), "=r"(R3) : "r"(a))

__device__ __forceinline__ void mma_f16(float* c, const uint32_t* a, const uint32_t* b) {
    asm volatile(
        "mma.sync.aligned.m16n8k16.row.col.f32.f16.f16.f32 "
        "{%0,%1,%2,%3}, {%4,%5,%6,%7}, {%8,%9}, {%0,%1,%2,%3};"
        : "+f"(c[0]), "+f"(c[1]), "+f"(c[2]), "+f"(c[3])
        : "r"(a[0]), "r"(a[1]), "r"(a[2]), "r"(a[3]), "r"(b[0]), "r"(b[1]));
}

// ---------------- kernel A: offset net + tap precompute ----------------
__global__ void k_offsets(const float* __restrict__ lat,
                          const float* __restrict__ w1, const float* __restrict__ b1,
                          const float* __restrict__ w2, const float* __restrict__ b2) {
    __shared__ float sh[NB][64];
    __shared__ float soff[NB][18];
    int t = threadIdx.x;
    int n = t >> 6, o = t & 63;
    float acc = b1[o];
    for (int i = 0; i < CMID; i++)
        acc += lat[n * CMID + i] * w1[(o * CMID + i) * KK + 4];
    sh[n][o] = fmaxf(acc, 0.f);
    __syncthreads();
    if (t < NB * 18) {
        int nn = t / 18, j = t % 18;
        float a = b2[j];
        for (int q = 0; q < 64; q++)
            a += sh[nn][q] * w2[(j * 64 + q) * KK + 4];
        soff[nn][j] = tanhf(a);
    }
    __syncthreads();
    if (t < NB * KK) {
        int nn = t / KK, k = t % KK;
        float oy = soff[nn][2 * k], ox = soff[nn][2 * k + 1];
        float ay = (float)(k / 3 - 1) + oy;
        float ax = (float)(k % 3 - 1) + ox;
        float fy = floorf(ay), fx = floorf(ax);
        float dy = ay - fy, dx = ax - fx;
        g_tiy[nn][k] = (int)fy;
        g_tix[nn][k] = (int)fx;
        g_twgt[nn][k][0] = (1.f - dy) * (1.f - dx);
        g_twgt[nn][k][1] = (1.f - dy) * dx;
        g_twgt[nn][k][2] = dy * (1.f - dx);
        g_twgt[nn][k][3] = dy * dx;
    }
}

// ---------------- weight re-layout (both GEMM A operands) ----------------
// Transconv classes: cls = ry*2+rx; y-taps(ry): ry0->[ky=1,iofs=0]; ry1->[(ky=0,iofs=1),(ky=2,iofs=0)]
// k-layout within class: k = ci*nt + ty*ntx + tx ; offsets {0,256,768,1280}
__global__ void k_wprep(const float* __restrict__ w) {
    int e = blockIdx.x * 256 + threadIdx.x;   // < 294912
    {   // deform GEMM A: g_Wa[o][kc] ; kc = k*128 + c
        int o  = e / KC;
        int kc = e - o * KC;
        int c  = kc & 127, k = kc >> 7;
        g_Wa[o][kc] = __float2half_rn(w[(o * CMID + c) * KK + k]);
    }
    {   // transconv GEMM A: g_Wc[co][k], class-grouped
        int co = e / KTC;
        int k  = e - co * KTC;
        int ci, ky, kx;
        if (k < 256)       { ci = k; ky = 1; kx = 1; }
        else if (k < 768)  { int kk = k - 256;  ci = kk >> 1; ky = 1;               kx = (kk & 1) * 2; }
        else if (k < 1280) { int kk = k - 768;  ci = kk >> 1; ky = (kk & 1) * 2;    kx = 1; }
        else               { int kk = k - 1280; ci = kk >> 2; ky = ((kk >> 1) & 1) * 2; kx = (kk & 1) * 2; }
        g_Wc[co][k] = __float2half_rn(w[(ci * CMID + co) * KK + ky * 3 + kx]);
    }
}

// ---------------- x -> fp16 padded + shifted copies ----------------
__global__ void k_xprep(const float* __restrict__ x) {
    int idx = blockIdx.x * 256 + threadIdx.x;   // < 266240 = 33280 rows * 8 chunks
    int chunk = idx & 7;
    int row = idx >> 3;                 // (n*256+ci)*65 + u
    int u = row % 65;
    int nc = row / 65;
    int v0 = chunk * 8;
    __align__(16) __half ha[8];
    __align__(16) __half hb[8];
    if (u < 64) {
        const float* src = x + ((size_t)nc * 64 + u) * 64 + v0;
        #pragma unroll
        for (int p = 0; p < 8; p++) ha[p] = __float2half_rn(src[p]);
        #pragma unroll
        for (int p = 0; p < 8; p++) {
            hb[p] = __float2half_rn(0.f);
            if (v0 + p + 1 < 64) hb[p] = __float2half_rn(src[p + 1]);
        }
    } else {
        #pragma unroll
        for (int p = 0; p < 8; p++) { ha[p] = __float2half_rn(0.f); hb[p] = __float2half_rn(0.f); }
    }
    size_t dst = (size_t)row * 64 + v0;
    *reinterpret_cast<uint4*>(&g_xhA[dst]) = *reinterpret_cast<uint4*>(ha);
    *reinterpret_cast<uint4*>(&g_xhB[dst]) = *reinterpret_cast<uint4*>(hb);
}

// ---------------- kernel B: transposed conv as 4 parity-class HMMA GEMMs ----------------
// grid.x = 256: cls = bx>>6 (ry=cls>>1, rx=cls&1); colblk = bx&63: n = cb>>5, u0 = (cb&31)*2
// per class: M=128 (co), N=128 cols = (du in {0,1}) x (v in [0,64)), K = 256<<(ry+rx)
#define TLDA 40
#define TLDB 136
__global__ __launch_bounds__(256, 2) void k_tc() {
    __shared__ __half As[2][128][TLDA];
    __shared__ __half Bs[2][32][TLDB];

    const int bx = blockIdx.x;
    const int cls = bx >> 6, cb = bx & 63;
    const int ry = cls >> 1, rx = cls & 1;
    const int sh = ry + rx, nt = 1 << sh;
    const int n = cb >> 5, u0 = (cb & 31) << 1;
    const int koff = (cls == 0) ? 0 : (cls == 1) ? 256 : (cls == 2) ? 768 : 1280;
    const int nkt = 8 << sh;

    const int t = threadIdx.x, wid = t >> 5, lane = t & 31;
    const int gid = lane >> 2, tig = lane & 3, lr = lane & 7, lm = lane >> 3;
    const int wm = wid >> 2, wn = wid & 3;

    const uint32_t asb = smem_u32(&As[0][0][0]);
    const uint32_t bsb = smem_u32(&Bs[0][0][0]);
    const __half* Wc = &g_Wc[0][0];

    float acc[4][4][4];
    #pragma unroll
    for (int i = 0; i < 4; i++)
        #pragma unroll
        for (int j = 0; j < 4; j++)
            #pragma unroll
            for (int c = 0; c < 4; c++) acc[i][j][c] = 0.f;

    auto stage = [&](int buf, int k0) {
        // A: 128 rows x 32 k = 512 x 16B chunks
        #pragma unroll
        for (int h = 0; h < 2; h++) {
            int c = t + h * 256;
            int row = c >> 2, u4 = c & 3;
            CP16(asb + buf * (128 * TLDA * 2) + row * (TLDA * 2) + u4 * 16,
                 Wc + (size_t)row * KTC + koff + k0 + u4 * 8);
        }
        // B: 32 k-rows x 128 cols = 512 x 16B chunks (im2col from xhA/xhB)
        #pragma unroll
        for (int h = 0; h < 2; h++) {
            int c = t + h * 256;
            int row = c >> 4, rest = c & 15;
            int du = rest >> 3, vv = (rest & 7) * 8;
            int k = k0 + row;
            int ci = k >> sh, tt = k & (nt - 1);
            int ty = tt >> rx, tx = tt & rx;
            int iof = ry & (ty ^ 1);
            int jof = rx & (tx ^ 1);
            const __half* src = jof ? g_xhB : g_xhA;
            size_t ga = ((size_t)(n * CIN + ci) * 65 + (u0 + du + iof)) * 64 + vv;
            CP16(bsb + buf * (32 * TLDB * 2) + row * (TLDB * 2) + (du * 64 + vv) * 2,
                 src + ga);
        }
    };

    stage(0, 0);
    CP_COMMIT();

    for (int kt = 0; kt < nkt; kt++) {
        const int cur = kt & 1;
        if (kt + 1 < nkt) {
            stage(cur ^ 1, (kt + 1) * 32);
            CP_COMMIT();
            CP_WAIT1();
        } else {
            CP_WAIT0();
        }
        __syncthreads();

        const uint32_t as = asb + cur * (128 * TLDA * 2);
        const uint32_t bs = bsb + cur * (32 * TLDB * 2);

        #pragma unroll
        for (int ks = 0; ks < 2; ks++) {
            uint32_t a[4][4], b[4][2];
            #pragma unroll
            for (int mf = 0; mf < 4; mf++) {
                uint32_t row = wm * 64 + mf * 16 + ((lm & 1) << 3) + lr;
                uint32_t colb = ks * 32 + ((lm >> 1) << 4);
                LDSM4(a[mf][0], a[mf][1], a[mf][2], a[mf][3],
                      as + row * (TLDA * 2) + colb);
            }
            #pragma unroll
            for (int np = 0; np < 2; np++) {
                uint32_t r0, r1, r2, r3;
                // trans load of Bs[k][n]: g bit0 -> +8 k, g bit1 -> +8 n
                uint32_t krow = ks * 16 + ((lm & 1) << 3) + lr;
                uint32_t ncol = wn * 32 + np * 16 + ((lm >> 1) << 3);
                LDSM4T(r0, r1, r2, r3, bs + krow * (TLDB * 2) + ncol * 2);
                b[2 * np][0] = r0;     b[2 * np][1] = r1;
                b[2 * np + 1][0] = r2; b[2 * np + 1][1] = r3;
            }
            #pragma unroll
            for (int mf = 0; mf < 4; mf++)
                #pragma unroll
                for (int nf = 0; nf < 4; nf++)
                    mma_f16(acc[mf][nf], a[mf], b[nf]);
        }
        __syncthreads();
    }

    // epilogue: col nn -> (du = nn>>6, v = nn&63); Y = 2*(u0+du)+ry, X = 2*v+rx
    #pragma unroll
    for (int mf = 0; mf < 4; mf++) {
        int m = wm * 64 + mf * 16 + gid;
        #pragma unroll
        for (int nf = 0; nf < 4; nf++) {
            int nn = wn * 32 + nf * 8 + tig * 2;
            int du = nn >> 6, v = nn & 63;
            int Y = 2 * (u0 + du) + ry;
            int X = 2 * v + rx;
            g_up[n][m][Y][X]         = acc[mf][nf][0];
            g_up[n][m][Y][X + 2]     = acc[mf][nf][1];
            g_up[n][m + 8][Y][X]     = acc[mf][nf][2];
            g_up[n][m + 8][Y][X + 2] = acc[mf][nf][3];
        }
    }
}

// ---------------- kernel C1: bilinear gather -> transposed [q][kc] fp16 ----------------
__global__ __launch_bounds__(256) void k_sample() {
    __shared__ float s_t[64][133];
    const int kb = blockIdx.x;
    const int by = blockIdx.y;
    const int n = by >> 7, y = by & 127;
    const int kc0 = kb * 64;
    const int k = kc0 >> 7;
    const int c0 = kc0 & 127;
    const int t = threadIdx.x;

    const int iy = g_tiy[n][k], ix = g_tix[n][k];
    const float w00 = g_twgt[n][k][0], w01 = g_twgt[n][k][1];
    const float w10 = g_twgt[n][k][2], w11 = g_twgt[n][k][3];

    const int r0 = y + iy, r1 = r0 + 1;
    const bool v0 = (r0 >= 0) && (r0 < H);
    const bool v1 = (r1 >= 0) && (r1 < H);

    #pragma unroll
    for (int it = 0; it < 8; it++) {
        int e = t + it * 256;
        int kcl = e >> 5;
        int xq  = e & 31;
        int x0  = xq << 2;
        const float* U = &g_up[n][c0 + kcl][0][0];
        int cb = x0 + ix;
        float row0[5], row1[5];
        #pragma unroll
        for (int u = 0; u < 5; u++) {
            int col = cb + u;
            bool vc = (col >= 0) && (col < W);
            row0[u] = (v0 && vc) ? U[r0 * W + col] : 0.f;
            row1[u] = (v1 && vc) ? U[r1 * W + col] : 0.f;
        }
        s_t[kcl][x0 + 0] = w00 * row0[0] + w01 * row0[1] + w10 * row1[0] + w11 * row1[1];
        s_t[kcl][x0 + 1] = w00 * row0[1] + w01 * row0[2] + w10 * row1[1] + w11 * row1[2];
        s_t[kcl][x0 + 2] = w00 * row0[2] + w01 * row0[3] + w10 * row1[2] + w11 * row1[3];
        s_t[kcl][x0 + 3] = w00 * row0[3] + w01 * row0[4] + w10 * row1[3] + w11 * row1[4];
    }
    __syncthreads();

    #pragma unroll
    for (int it = 0; it < 4; it++) {
        int f = t + it * 256;
        int x  = f >> 3;
        int u8 = f & 7;
        uint32_t hw[4];
        #pragma unroll
        for (int p = 0; p < 4; p++) {
            __half2 h2;
            h2.x = __float2half_rn(s_t[u8 * 8 + 2 * p][x]);
            h2.y = __float2half_rn(s_t[u8 * 8 + 2 * p + 1][x]);
            hw[p] = *reinterpret_cast<uint32_t*>(&h2);
        }
        size_t q = ((size_t)n << 14) + (y << 7) + x;
        *reinterpret_cast<uint4*>(&g_ST[q][kc0 + u8 * 8]) =
            make_uint4(hw[0], hw[1], hw[2], hw[3]);
    }
}

// ---------------- kernel C2: single-segment fp16 HMMA GEMM ----------------
#define BK      32
#define NTILE   36            // 1152 / 32
#define LDH     40
#define STG     (128 * LDH)

__global__ __launch_bounds__(256, 2) void k_gemm(float* __restrict__ out) {
    __shared__ __half As[2][128][LDH];
    __shared__ __half Bs[2][128][LDH];

    const int nb = blockIdx.x;
    const int mb = blockIdx.y;
    const int t  = threadIdx.x;
    const int wid = t >> 5, lane = t & 31;
    const int gid = lane >> 2, tig = lane & 3;
    const int lr = lane & 7, lm = lane >> 3;
    const int wm = wid >> 2, wn = wid & 3;
    const int m0 = mb * 128, n0 = nb * 128;

    const uint32_t asb0 = smem_u32(&As[0][0][0]);
    const uint32_t bsb0 = smem_u32(&Bs[0][0][0]);

    const int sc0 = t * 2;
    const int srow0 = sc0 >> 2, su0 = sc0 & 3;
    const int srow1 = (sc0 + 1) >> 2, su1 = (sc0 + 1) & 3;

    const __half* Ab = &g_Wa[m0][0];
    const __half* Bb = &g_ST[n0][0];

    float acc[4][4][4];
    #pragma unroll
    for (int i = 0; i < 4; i++)
        #pragma unroll
        for (int j = 0; j < 4; j++)
            #pragma unroll
            for (int c = 0; c < 4; c++) acc[i][j][c] = 0.f;

    {   // prologue: tile 0 -> buffer 0
        CP16(asb0 + srow0 * (LDH * 2) + su0 * 16, Ab + (size_t)srow0 * KC + su0 * 8);
        CP16(asb0 + srow1 * (LDH * 2) + su1 * 16, Ab + (size_t)srow1 * KC + su1 * 8);
        CP16(bsb0 + srow0 * (LDH * 2) + su0 * 16, Bb + (size_t)srow0 * KC + su0 * 8);
        CP16(bsb0 + srow1 * (LDH * 2) + su1 * 16, Bb + (size_t)srow1 * KC + su1 * 8);
        CP_COMMIT();
    }

    for (int kt = 0; kt < NTILE; kt++) {
        const int cur = kt & 1;
        if (kt + 1 < NTILE) {
            const int k0 = (kt + 1) * BK;
            const uint32_t as = asb0 + (cur ^ 1) * (STG * 2);
            const uint32_t bs = bsb0 + (cur ^ 1) * (STG * 2);
            const __half* Ag = Ab + k0;
            const __half* Bg = Bb + k0;
            CP16(as + srow0 * (LDH * 2) + su0 * 16, Ag + (size_t)srow0 * KC + su0 * 8);
            CP16(as + srow1 * (LDH * 2) + su1 * 16, Ag + (size_t)srow1 * KC + su1 * 8);
            CP16(bs + srow0 * (LDH * 2) + su0 * 16, Bg + (size_t)srow0 * KC + su0 * 8);
            CP16(bs + srow1 * (LDH * 2) + su1 * 16, Bg + (size_t)srow1 * KC + su1 * 8);
            CP_COMMIT();
            CP_WAIT1();
        } else {
            CP_WAIT0();
        }
        __syncthreads();

        const uint32_t as = asb0 + cur * (STG * 2);
        const uint32_t bs = bsb0 + cur * (STG * 2);

        #pragma unroll
        for (int ks = 0; ks < 2; ks++) {
            uint32_t a[4][4], b[4][2];
            #pragma unroll
            for (int mf = 0; mf < 4; mf++) {
                uint32_t row = wm * 64 + mf * 16 + ((lm & 1) << 3) + lr;
                uint32_t colb = ks * 32 + ((lm >> 1) << 4);
                LDSM4(a[mf][0], a[mf][1], a[mf][2], a[mf][3],
                      as + row * (LDH * 2) + colb);
            }
            #pragma unroll
            for (int np = 0; np < 2; np++) {
                uint32_t r0, r1, r2, r3;
                uint32_t row = wn * 32 + np * 16 + ((lm >> 1) << 3) + lr;
                uint32_t colb = ks * 32 + ((lm & 1) << 4);
                LDSM4(r0, r1, r2, r3, bs + row * (LDH * 2) + colb);
                b[2 * np][0] = r0;     b[2 * np][1] = r1;
                b[2 * np + 1][0] = r2; b[2 * np + 1][1] = r3;
            }
            #pragma unroll
            for (int mf = 0; mf < 4; mf++)
                #pragma unroll
                for (int nf = 0; nf < 4; nf++)
                    mma_f16(acc[mf][nf], a[mf], b[nf]);
        }
        __syncthreads();
    }

    const int nbat = n0 >> 14;
    const int pix0 = n0 & 16383;
    #pragma unroll
    for (int mf = 0; mf < 4; mf++) {
        int o = m0 + wm * 64 + mf * 16 + gid;
        #pragma unroll
        for (int nf = 0; nf < 4; nf++) {
            int qoff = pix0 + wn * 32 + nf * 8 + tig * 2;
            float* d0 = out + ((size_t)nbat * CIN + o) * NPIX + qoff;
            *reinterpret_cast<float2*>(d0) = make_float2(acc[mf][nf][0], acc[mf][nf][1]);
            float* d1 = out + ((size_t)nbat * CIN + o + 8) * NPIX + qoff;
            *reinterpret_cast<float2*>(d1) = make_float2(acc[mf][nf][2], acc[mf][nf][3]);
        }
    }
}

// ---------------- launch ----------------
extern "C" void kernel_launch(void* const* d_in, const int* in_sizes, int n_in,
                              void* d_out, int out_size) {
    const float* x   = (const float*)d_in[0];   // [2,256,64,64]
    const float* lat = (const float*)d_in[1];   // [2,128,1,1]
    const float* tw  = (const float*)d_in[2];   // [256,128,3,3]
    const float* w1  = (const float*)d_in[3];   // [64,128,3,3]
    const float* b1  = (const float*)d_in[4];   // [64]
    const float* w2  = (const float*)d_in[5];   // [18,64,3,3]
    const float* b2  = (const float*)d_in[6];   // [18]
    float* out = (float*)d_out;                 // [2,256,128,128]

    k_offsets<<<1, 128>>>(lat, w1, b1, w2, b2);
    k_wprep<<<1152, 256>>>(tw);
    k_xprep<<<1040, 256>>>(x);
    k_tc<<<256, 256>>>();
    k_sample<<<dim3(18, 256), 256>>>();
    k_gemm<<<dim3(256, 2), 256>>>(out);
}

// round 8
// speedup vs baseline: 3.9508x; 1.2075x over previous
#include <cuda_runtime.h>
#include <cuda_fp16.h>
#include <cstdint>
#include <math.h>

#define NB   2
#define CIN  256     // deform output channels O (GEMM M); also transconv input channels
#define CMID 128     // transconv output channels
#define H0   64
#define W0   64
#define H    128
#define W    128
#define KK   9
#define KC   1152    // KK * CMID
#define NPIX 16384
#define QTOT 32768   // GEMM N total
#define KTC  2304    // transconv class-grouped K total (256+512+512+1024)

// ---------------- device scratch ----------------
__device__ float  g_up[NB][CMID][H][W];      // transposed-conv output
__device__ __half g_ST[KC][QTOT];            // im2col, [kc][q] N-contiguous, fp16
__device__ __half g_Wa[CIN][KC];             // deform GEMM A, m-major k-contig, fp16
__device__ __half g_Wc[CMID][KTC];           // transconv GEMM A, class-grouped k
__device__ __half g_xhA[NB * CIN * 65 * 64]; // x fp16, padded (zero row u=64)
__device__ __half g_xhB[NB * CIN * 65 * 64]; // x shifted by +1 in j (zero fill)
__device__ int    g_tiy[NB][KK];
__device__ int    g_tix[NB][KK];
__device__ float  g_twgt[NB][KK][4];

__device__ __forceinline__ uint32_t smem_u32(const void* p) {
    uint32_t a;
    asm("{ .reg .u64 t; cvta.to.shared.u64 t, %1; cvt.u32.u64 %0, t; }" : "=r"(a) : "l"(p));
    return a;
}

#define CP16(sm, gp) \
    asm volatile("cp.async.cg.shared.global [%0], [%1], 16;" :: "r"(sm), "l"(gp) : "memory")
#define CP_COMMIT() asm volatile("cp.async.commit_group;" ::: "memory")
#define CP_WAIT1()  asm volatile("cp.async.wait_group 1;" ::: "memory")
#define CP_WAIT0()  asm volatile("cp.async.wait_group 0;" ::: "memory")

#define LDSM4(R0, R1, R2, R3, a) \
    asm volatile("ldmatrix.sync.aligned.m8n8.x4.shared.b16 {%0,%1,%2,%3}, [%4];" \
                 : "=r"(R0), "=r"(R1), "=r"(R2), "=r"(R3) : "r"(a))
#define LDSM4T(R0, R1, R2, R3, a) \
    asm volatile("ldmatrix.sync.aligned.m8n8.x4.trans.shared.b16 {%0,%1,%2,%3}, [%4];" \
                 : "=r"(R0), "=r"(R1), "=r"(R2), "=r"(R3) : "r"(a))

__device__ __forceinline__ void mma_f16(float* c, const uint32_t* a, const uint32_t* b) {
    asm volatile(
        "mma.sync.aligned.m16n8k16.row.col.f32.f16.f16.f32 "
        "{%0,%1,%2,%3}, {%4,%5,%6,%7}, {%8,%9}, {%0,%1,%2,%3};"
        : "+f"(c[0]), "+f"(c[1]), "+f"(c[2]), "+f"(c[3])
        : "r"(a[0]), "r"(a[1]), "r"(a[2]), "r"(a[3]), "r"(b[0]), "r"(b[1]));
}

// ---------------- kernel A: offset net + tap precompute ----------------
__global__ void k_offsets(const float* __restrict__ lat,
                          const float* __restrict__ w1, const float* __restrict__ b1,
                          const float* __restrict__ w2, const float* __restrict__ b2) {
    __shared__ float sh[NB][64];
    __shared__ float soff[NB][18];
    int t = threadIdx.x;
    int n = t >> 6, o = t & 63;
    float acc = b1[o];
    for (int i = 0; i < CMID; i++)
        acc += lat[n * CMID + i] * w1[(o * CMID + i) * KK + 4];
    sh[n][o] = fmaxf(acc, 0.f);
    __syncthreads();
    if (t < NB * 18) {
        int nn = t / 18, j = t % 18;
        float a = b2[j];
        for (int q = 0; q < 64; q++)
            a += sh[nn][q] * w2[(j * 64 + q) * KK + 4];
        soff[nn][j] = tanhf(a);
    }
    __syncthreads();
    if (t < NB * KK) {
        int nn = t / KK, k = t % KK;
        float oy = soff[nn][2 * k], ox = soff[nn][2 * k + 1];
        float ay = (float)(k / 3 - 1) + oy;
        float ax = (float)(k % 3 - 1) + ox;
        float fy = floorf(ay), fx = floorf(ax);
        float dy = ay - fy, dx = ax - fx;
        g_tiy[nn][k] = (int)fy;
        g_tix[nn][k] = (int)fx;
        g_twgt[nn][k][0] = (1.f - dy) * (1.f - dx);
        g_twgt[nn][k][1] = (1.f - dy) * dx;
        g_twgt[nn][k][2] = dy * (1.f - dx);
        g_twgt[nn][k][3] = dy * dx;
    }
}

// ---------------- merged prep: weights re-layout + x fp16 copies ----------------
__global__ void k_prep(const float* __restrict__ w, const float* __restrict__ x) {
    int b = blockIdx.x;
    if (b < 1152) {
        int e = b * 256 + threadIdx.x;   // < 294912
        {   // deform GEMM A: g_Wa[o][kc] ; kc = k*128 + c
            int o  = e / KC;
            int kc = e - o * KC;
            int c  = kc & 127, k = kc >> 7;
            g_Wa[o][kc] = __float2half_rn(w[(o * CMID + c) * KK + k]);
        }
        {   // transconv GEMM A: g_Wc[co][k], class-grouped
            int co = e / KTC;
            int k  = e - co * KTC;
            int ci, ky, kx;
            if (k < 256)       { ci = k; ky = 1; kx = 1; }
            else if (k < 768)  { int kk = k - 256;  ci = kk >> 1; ky = 1;               kx = (kk & 1) * 2; }
            else if (k < 1280) { int kk = k - 768;  ci = kk >> 1; ky = (kk & 1) * 2;    kx = 1; }
            else               { int kk = k - 1280; ci = kk >> 2; ky = ((kk >> 1) & 1) * 2; kx = (kk & 1) * 2; }
            g_Wc[co][k] = __float2half_rn(w[(ci * CMID + co) * KK + ky * 3 + kx]);
        }
    } else {
        int idx = (b - 1152) * 256 + threadIdx.x;   // < 266240
        if (idx >= 266240) return;
        int chunk = idx & 7;
        int row = idx >> 3;                 // (n*256+ci)*65 + u
        int u = row % 65;
        int nc = row / 65;
        int v0 = chunk * 8;
        __align__(16) __half ha[8];
        __align__(16) __half hb[8];
        if (u < 64) {
            const float* src = x + ((size_t)nc * 64 + u) * 64 + v0;
            #pragma unroll
            for (int p = 0; p < 8; p++) ha[p] = __float2half_rn(src[p]);
            #pragma unroll
            for (int p = 0; p < 8; p++) {
                hb[p] = __float2half_rn(0.f);
                if (v0 + p + 1 < 64) hb[p] = __float2half_rn(src[p + 1]);
            }
        } else {
            #pragma unroll
            for (int p = 0; p < 8; p++) { ha[p] = __float2half_rn(0.f); hb[p] = __float2half_rn(0.f); }
        }
        size_t dst = (size_t)row * 64 + v0;
        *reinterpret_cast<uint4*>(&g_xhA[dst]) = *reinterpret_cast<uint4*>(ha);
        *reinterpret_cast<uint4*>(&g_xhB[dst]) = *reinterpret_cast<uint4*>(hb);
    }
}

// ---------------- kernel B: transposed conv as 4 parity-class HMMA GEMMs ----------------
// heavy classes first: cls = 3 - (bx>>6)
#define TLDA 40
#define TLDB 136
__global__ __launch_bounds__(256, 2) void k_tc() {
    __shared__ __half As[2][128][TLDA];
    __shared__ __half Bs[2][32][TLDB];

    const int bx = blockIdx.x;
    const int cls = 3 - (bx >> 6), cb = bx & 63;
    const int ry = cls >> 1, rx = cls & 1;
    const int sh = ry + rx, nt = 1 << sh;
    const int n = cb >> 5, u0 = (cb & 31) << 1;
    const int koff = (cls == 0) ? 0 : (cls == 1) ? 256 : (cls == 2) ? 768 : 1280;
    const int nkt = 8 << sh;

    const int t = threadIdx.x, wid = t >> 5, lane = t & 31;
    const int gid = lane >> 2, tig = lane & 3, lr = lane & 7, lm = lane >> 3;
    const int wm = wid >> 2, wn = wid & 3;

    const uint32_t asb = smem_u32(&As[0][0][0]);
    const uint32_t bsb = smem_u32(&Bs[0][0][0]);
    const __half* Wc = &g_Wc[0][0];

    float acc[4][4][4];
    #pragma unroll
    for (int i = 0; i < 4; i++)
        #pragma unroll
        for (int j = 0; j < 4; j++)
            #pragma unroll
            for (int c = 0; c < 4; c++) acc[i][j][c] = 0.f;

    auto stage = [&](int buf, int k0) {
        #pragma unroll
        for (int h = 0; h < 2; h++) {
            int c = t + h * 256;
            int row = c >> 2, u4 = c & 3;
            CP16(asb + buf * (128 * TLDA * 2) + row * (TLDA * 2) + u4 * 16,
                 Wc + (size_t)row * KTC + koff + k0 + u4 * 8);
        }
        #pragma unroll
        for (int h = 0; h < 2; h++) {
            int c = t + h * 256;
            int row = c >> 4, rest = c & 15;
            int du = rest >> 3, vv = (rest & 7) * 8;
            int k = k0 + row;
            int ci = k >> sh, tt = k & (nt - 1);
            int ty = tt >> rx, tx = tt & rx;
            int iof = ry & (ty ^ 1);
            int jof = rx & (tx ^ 1);
            const __half* src = jof ? g_xhB : g_xhA;
            size_t ga = ((size_t)(n * CIN + ci) * 65 + (u0 + du + iof)) * 64 + vv;
            CP16(bsb + buf * (32 * TLDB * 2) + row * (TLDB * 2) + (du * 64 + vv) * 2,
                 src + ga);
        }
    };

    stage(0, 0);
    CP_COMMIT();

    for (int kt = 0; kt < nkt; kt++) {
        const int cur = kt & 1;
        if (kt + 1 < nkt) {
            stage(cur ^ 1, (kt + 1) * 32);
            CP_COMMIT();
            CP_WAIT1();
        } else {
            CP_WAIT0();
        }
        __syncthreads();

        const uint32_t as = asb + cur * (128 * TLDA * 2);
        const uint32_t bs = bsb + cur * (32 * TLDB * 2);

        #pragma unroll
        for (int ks = 0; ks < 2; ks++) {
            uint32_t a[4][4], b[4][2];
            #pragma unroll
            for (int mf = 0; mf < 4; mf++) {
                uint32_t row = wm * 64 + mf * 16 + ((lm & 1) << 3) + lr;
                uint32_t colb = ks * 32 + ((lm >> 1) << 4);
                LDSM4(a[mf][0], a[mf][1], a[mf][2], a[mf][3],
                      as + row * (TLDA * 2) + colb);
            }
            #pragma unroll
            for (int np = 0; np < 2; np++) {
                uint32_t r0, r1, r2, r3;
                uint32_t krow = ks * 16 + ((lm & 1) << 3) + lr;
                uint32_t ncol = wn * 32 + np * 16 + ((lm >> 1) << 3);
                LDSM4T(r0, r1, r2, r3, bs + krow * (TLDB * 2) + ncol * 2);
                b[2 * np][0] = r0;     b[2 * np][1] = r1;
                b[2 * np + 1][0] = r2; b[2 * np + 1][1] = r3;
            }
            #pragma unroll
            for (int mf = 0; mf < 4; mf++)
                #pragma unroll
                for (int nf = 0; nf < 4; nf++)
                    mma_f16(acc[mf][nf], a[mf], b[nf]);
        }
        __syncthreads();
    }

    #pragma unroll
    for (int mf = 0; mf < 4; mf++) {
        int m = wm * 64 + mf * 16 + gid;
        #pragma unroll
        for (int nf = 0; nf < 4; nf++) {
            int nn = wn * 32 + nf * 8 + tig * 2;
            int du = nn >> 6, v = nn & 63;
            int Y = 2 * (u0 + du) + ry;
            int X = 2 * v + rx;
            g_up[n][m][Y][X]         = acc[mf][nf][0];
            g_up[n][m][Y][X + 2]     = acc[mf][nf][1];
            g_up[n][m + 8][Y][X]     = acc[mf][nf][2];
            g_up[n][m + 8][Y][X + 2] = acc[mf][nf][3];
        }
    }
}

// ---------------- kernel C1: bilinear gather -> [kc][q] fp16 (direct, no transpose) ----------------
__global__ __launch_bounds__(256) void k_sample() {
    int idx = blockIdx.x * 256 + threadIdx.x;   // 9,437,184 threads, 4 q each
    int e = idx << 2;
    int x0 = e & 127;
    int y  = (e >> 7) & 127;
    int n  = (e >> 14) & 1;
    int kc = e >> 15;                  // 0..1151
    int c  = kc & 127, k = kc >> 7;

    int iy = g_tiy[n][k], ix = g_tix[n][k];
    float w00 = g_twgt[n][k][0], w01 = g_twgt[n][k][1];
    float w10 = g_twgt[n][k][2], w11 = g_twgt[n][k][3];

    const float* U = &g_up[n][c][0][0];
    int r0 = y + iy, r1 = r0 + 1;
    bool v0 = (r0 >= 0) && (r0 < H);
    bool v1 = (r1 >= 0) && (r1 < H);
    int cb = x0 + ix;

    float row0[5], row1[5];
    #pragma unroll
    for (int u = 0; u < 5; u++) {
        int col = cb + u;
        bool vc = (col >= 0) && (col < W);
        row0[u] = (v0 && vc) ? U[r0 * W + col] : 0.f;
        row1[u] = (v1 && vc) ? U[r1 * W + col] : 0.f;
    }
    __half2 p0, p1;
    p0.x = __float2half_rn(w00 * row0[0] + w01 * row0[1] + w10 * row1[0] + w11 * row1[1]);
    p0.y = __float2half_rn(w00 * row0[1] + w01 * row0[2] + w10 * row1[1] + w11 * row1[2]);
    p1.x = __float2half_rn(w00 * row0[2] + w01 * row0[3] + w10 * row1[2] + w11 * row1[3]);
    p1.y = __float2half_rn(w00 * row0[3] + w01 * row0[4] + w10 * row1[3] + w11 * row1[4]);

    int q0 = (n << 14) + (y << 7) + x0;
    __half2* dst = reinterpret_cast<__half2*>(&g_ST[kc][q0]);
    dst[0] = p0;
    dst[1] = p1;
}

// ---------------- kernel C2: fp16 HMMA GEMM, B K-major [kc][q] ----------------
#define BK      32
#define NTILE   36            // 1152 / 32
#define LDH     40
#define LDB     136

__global__ __launch_bounds__(256, 2) void k_gemm(float* __restrict__ out) {
    __shared__ __half As[2][128][LDH];
    __shared__ __half Bs[2][32][LDB];

    const int nb = blockIdx.x;           // 256 N-blocks of 128 q
    const int mb = blockIdx.y;           // 2 M-blocks of 128 o
    const int t  = threadIdx.x;
    const int wid = t >> 5, lane = t & 31;
    const int gid = lane >> 2, tig = lane & 3;
    const int lr = lane & 7, lm = lane >> 3;
    const int wm = wid >> 2, wn = wid & 3;
    const int m0 = mb * 128, n0 = nb * 128;

    const uint32_t asb = smem_u32(&As[0][0][0]);
    const uint32_t bsb = smem_u32(&Bs[0][0][0]);

    const __half* Ab = &g_Wa[m0][0];
    const __half* Bg = &g_ST[0][0];

    float acc[4][4][4];
    #pragma unroll
    for (int i = 0; i < 4; i++)
        #pragma unroll
        for (int j = 0; j < 4; j++)
            #pragma unroll
            for (int c = 0; c < 4; c++) acc[i][j][c] = 0.f;

    auto stage = [&](int buf, int k0) {
        // A: 128 rows x 32 k = 512 x 16B
        #pragma unroll
        for (int h = 0; h < 2; h++) {
            int c = t + h * 256;
            int row = c >> 2, u4 = c & 3;
            CP16(asb + buf * (128 * LDH * 2) + row * (LDH * 2) + u4 * 16,
                 Ab + (size_t)row * KC + k0 + u4 * 8);
        }
        // B: 32 k-rows x 128 q = 512 x 16B
        #pragma unroll
        for (int h = 0; h < 2; h++) {
            int c = t + h * 256;
            int row = c >> 4, vv = (c & 15) * 8;
            CP16(bsb + buf * (32 * LDB * 2) + row * (LDB * 2) + vv * 2,
                 Bg + (size_t)(k0 + row) * QTOT + n0 + vv);
        }
    };

    stage(0, 0);
    CP_COMMIT();

    for (int kt = 0; kt < NTILE; kt++) {
        const int cur = kt & 1;
        if (kt + 1 < NTILE) {
            stage(cur ^ 1, (kt + 1) * BK);
            CP_COMMIT();
            CP_WAIT1();
        } else {
            CP_WAIT0();
        }
        __syncthreads();

        const uint32_t as = asb + cur * (128 * LDH * 2);
        const uint32_t bs = bsb + cur * (32 * LDB * 2);

        #pragma unroll
        for (int ks = 0; ks < 2; ks++) {
            uint32_t a[4][4], b[4][2];
            #pragma unroll
            for (int mf = 0; mf < 4; mf++) {
                uint32_t row = wm * 64 + mf * 16 + ((lm & 1) << 3) + lr;
                uint32_t colb = ks * 32 + ((lm >> 1) << 4);
                LDSM4(a[mf][0], a[mf][1], a[mf][2], a[mf][3],
                      as + row * (LDH * 2) + colb);
            }
            #pragma unroll
            for (int np = 0; np < 2; np++) {
                uint32_t r0, r1, r2, r3;
                uint32_t krow = ks * 16 + ((lm & 1) << 3) + lr;
                uint32_t ncol = wn * 32 + np * 16 + ((lm >> 1) << 3);
                LDSM4T(r0, r1, r2, r3, bs + krow * (LDB * 2) + ncol * 2);
                b[2 * np][0] = r0;     b[2 * np][1] = r1;
                b[2 * np + 1][0] = r2; b[2 * np + 1][1] = r3;
            }
            #pragma unroll
            for (int mf = 0; mf < 4; mf++)
                #pragma unroll
                for (int nf = 0; nf < 4; nf++)
                    mma_f16(acc[mf][nf], a[mf], b[nf]);
        }
        __syncthreads();
    }

    const int nbat = n0 >> 14;
    const int pix0 = n0 & 16383;
    #pragma unroll
    for (int mf = 0; mf < 4; mf++) {
        int o = m0 + wm * 64 + mf * 16 + gid;
        #pragma unroll
        for (int nf = 0; nf < 4; nf++) {
            int qoff = pix0 + wn * 32 + nf * 8 + tig * 2;
            float* d0 = out + ((size_t)nbat * CIN + o) * NPIX + qoff;
            *reinterpret_cast<float2*>(d0) = make_float2(acc[mf][nf][0], acc[mf][nf][1]);
            float* d1 = out + ((size_t)nbat * CIN + o + 8) * NPIX + qoff;
            *reinterpret_cast<float2*>(d1) = make_float2(acc[mf][nf][2], acc[mf][nf][3]);
        }
    }
}

// ---------------- launch ----------------
extern "C" void kernel_launch(void* const* d_in, const int* in_sizes, int n_in,
                              void* d_out, int out_size) {
    const float* x   = (const float*)d_in[0];   // [2,256,64,64]
    const float* lat = (const float*)d_in[1];   // [2,128,1,1]
    const float* tw  = (const float*)d_in[2];   // [256,128,3,3]
    const float* w1  = (const float*)d_in[3];   // [64,128,3,3]
    const float* b1  = (const float*)d_in[4];   // [64]
    const float* w2  = (const float*)d_in[5];   // [18,64,3,3]
    const float* b2  = (const float*)d_in[6];   // [18]
    float* out = (float*)d_out;                 // [2,256,128,128]

    k_offsets<<<1, 128>>>(lat, w1, b1, w2, b2);
    k_prep<<<2192, 256>>>(tw, x);
    k_tc<<<256, 256>>>();
    k_sample<<<36864, 256>>>();
    k_gemm<<<dim3(256, 2), 256>>>(out);
}